// round 1
// baseline (speedup 1.0000x reference)
#include <cuda_runtime.h>
#include <math.h>

// ---------------------------------------------------------------------------
// LegalMultiHeadAttention: 4-head MHA with per-head projections.
//   B=2, S=4096, D_MODEL=1024, H=4, D_K=256.
// Outputs (concatenated in d_out): out [B,S,1024] then attn [H,B,S,S].
// Round 1: fp32 SMEM-tiled SGEMMs (128x128x16, 8x8 microtile) + row softmax.
// ---------------------------------------------------------------------------

#define SEQ    4096
#define DK     256
#define DM     1024
#define NH     4
#define NB     2
#define BS_TOT (NB*SEQ)          // 8192

// Scratch (allocation-free rule: __device__ globals)
__device__ float g_Q[NH*BS_TOT*DK];            // [H,B,S,Dk]  32 MB
__device__ float g_K[NH*BS_TOT*DK];
__device__ float g_V[NH*BS_TOT*DK];
__device__ float g_HO[BS_TOT*DM];              // [B,S,H*Dk]  32 MB
__device__ float g_attn_fallback[(size_t)NH*NB*SEQ*SEQ];  // only used if attn isn't an output

// ---------------------------------------------------------------------------
// 128x128 tile SGEMM body. C[M,N] = alpha * A @ op(B) (+ bias[col]).
//   A: row-major [M,K], lda
//   B: TRANSB=false -> row-major [K,N], ldb ; TRANSB=true -> row-major [N,K], ldb
// All dims assumed multiples of the tile (true for every call here).
// ---------------------------------------------------------------------------
template<bool TRANSB, bool HASBIAS>
__device__ __forceinline__ void gemm128x128(
    const float* __restrict__ A, int lda,
    const float* __restrict__ B, int ldb,
    float* __restrict__ C, int ldc,
    int K, float alpha, const float* __restrict__ bias)
{
    __shared__ float As[16][128];
    __shared__ float Bs[16][128];

    const int tid = threadIdx.x;      // 256 threads
    const int tx  = tid & 15;
    const int ty  = tid >> 4;
    const long bm = (long)blockIdx.y * 128;
    const long bn = (long)blockIdx.x * 128;

    float acc[8][8];
#pragma unroll
    for (int i = 0; i < 8; i++)
#pragma unroll
        for (int j = 0; j < 8; j++) acc[i][j] = 0.0f;

    // staging indices
    const int lr = tid >> 1;          // 0..127 : M-row (A) / N-row (B^T)
    const int lc = (tid & 1) * 8;     // 0 or 8 : k-offset
    const int br = tid >> 4;          // 0..15  : k-row (B, NN)
    const int bc = (tid & 15) * 8;    // 0..120 : n-offset (B, NN)

    for (int kt = 0; kt < K; kt += 16) {
        {   // A tile -> As[k][m] (transposed)
            const float4* ap = reinterpret_cast<const float4*>(
                &A[(bm + lr) * (long)lda + kt + lc]);
            float4 a0 = ap[0], a1 = ap[1];
            As[lc+0][lr]=a0.x; As[lc+1][lr]=a0.y; As[lc+2][lr]=a0.z; As[lc+3][lr]=a0.w;
            As[lc+4][lr]=a1.x; As[lc+5][lr]=a1.y; As[lc+6][lr]=a1.z; As[lc+7][lr]=a1.w;
        }
        if (TRANSB) { // B[n,k] -> Bs[k][n] (transposed)
            const float4* bp = reinterpret_cast<const float4*>(
                &B[(bn + lr) * (long)ldb + kt + lc]);
            float4 b0 = bp[0], b1 = bp[1];
            Bs[lc+0][lr]=b0.x; Bs[lc+1][lr]=b0.y; Bs[lc+2][lr]=b0.z; Bs[lc+3][lr]=b0.w;
            Bs[lc+4][lr]=b1.x; Bs[lc+5][lr]=b1.y; Bs[lc+6][lr]=b1.z; Bs[lc+7][lr]=b1.w;
        } else {      // B[k,n] -> Bs[k][n] (direct, coalesced)
            const float4* bp = reinterpret_cast<const float4*>(
                &B[(kt + br) * (long)ldb + bn + bc]);
            float4 b0 = bp[0], b1 = bp[1];
            *reinterpret_cast<float4*>(&Bs[br][bc])     = b0;
            *reinterpret_cast<float4*>(&Bs[br][bc + 4]) = b1;
        }
        __syncthreads();

#pragma unroll
        for (int k = 0; k < 16; k++) {
            float a[8], b[8];
            float4 t;
            t = *reinterpret_cast<const float4*>(&As[k][ty*4]);      a[0]=t.x;a[1]=t.y;a[2]=t.z;a[3]=t.w;
            t = *reinterpret_cast<const float4*>(&As[k][64+ty*4]);   a[4]=t.x;a[5]=t.y;a[6]=t.z;a[7]=t.w;
            t = *reinterpret_cast<const float4*>(&Bs[k][tx*4]);      b[0]=t.x;b[1]=t.y;b[2]=t.z;b[3]=t.w;
            t = *reinterpret_cast<const float4*>(&Bs[k][64+tx*4]);   b[4]=t.x;b[5]=t.y;b[6]=t.z;b[7]=t.w;
#pragma unroll
            for (int i = 0; i < 8; i++)
#pragma unroll
                for (int j = 0; j < 8; j++)
                    acc[i][j] = fmaf(a[i], b[j], acc[i][j]);
        }
        __syncthreads();
    }

#pragma unroll
    for (int i = 0; i < 8; i++) {
        long row = bm + (i < 4 ? ty*4 + i : 64 + ty*4 + (i - 4));
#pragma unroll
        for (int j = 0; j < 8; j++) {
            int col = (int)bn + (j < 4 ? tx*4 + j : 64 + tx*4 + (j - 4));
            float v = acc[i][j] * alpha;
            if (HASBIAS) v += bias[col];
            C[row * (long)ldc + col] = v;
        }
    }
}

// --- 1) Q/K/V projections: grid (2, 64, 12): z = mat*4 + head -------------
__global__ void __launch_bounds__(256) proj_kernel(
    const float* __restrict__ q, const float* __restrict__ k, const float* __restrict__ v,
    const float* __restrict__ Wq, const float* __restrict__ bq,
    const float* __restrict__ Wk, const float* __restrict__ bk,
    const float* __restrict__ Wv, const float* __restrict__ bv)
{
    const int z    = blockIdx.z;
    const int mat  = z >> 2;
    const int head = z & 3;
    const float* A    = mat == 0 ? q  : mat == 1 ? k  : v;
    const float* W    = (mat == 0 ? Wq : mat == 1 ? Wk : Wv) + (size_t)head * DM * DK;
    const float* bias = (mat == 0 ? bq : mat == 1 ? bk : bv) + head * DK;
    float* C = (mat == 0 ? g_Q : mat == 1 ? g_K : g_V) + (size_t)head * BS_TOT * DK;
    gemm128x128<false, true>(A, DM, W, DK, C, DK, DM, 1.0f, bias);
}

// --- 2) scores = Q @ K^T * 1/sqrt(Dk): grid (32, 32, 8): z = h*NB + b ------
__global__ void __launch_bounds__(256) scores_kernel(float* __restrict__ attn_out)
{
    float* attn = attn_out ? attn_out : g_attn_fallback;
    const int z = blockIdx.z;
    const float* Q  = g_Q + (size_t)z * SEQ * DK;
    const float* Kh = g_K + (size_t)z * SEQ * DK;
    float* C = attn + (size_t)z * SEQ * SEQ;
    gemm128x128<true, false>(Q, DK, Kh, DK, C, SEQ, DK, 0.0625f, nullptr);
}

// --- 3) row softmax in place: grid 32768, 256 threads ----------------------
__global__ void __launch_bounds__(256) softmax_kernel(float* __restrict__ attn_out)
{
    float* attn = attn_out ? attn_out : g_attn_fallback;
    float* row = attn + (size_t)blockIdx.x * SEQ;
    const int tid = threadIdx.x;

    float v[16];
    float m = -1e30f;
#pragma unroll
    for (int i = 0; i < 16; i++) { v[i] = row[tid + i * 256]; m = fmaxf(m, v[i]); }

    __shared__ float red_max[8];
    __shared__ float red_sum[8];
#pragma unroll
    for (int o = 16; o > 0; o >>= 1) m = fmaxf(m, __shfl_xor_sync(0xffffffffu, m, o));
    if ((tid & 31) == 0) red_max[tid >> 5] = m;
    __syncthreads();
    float mb = red_max[0];
#pragma unroll
    for (int i = 1; i < 8; i++) mb = fmaxf(mb, red_max[i]);

    float s = 0.0f;
#pragma unroll
    for (int i = 0; i < 16; i++) { v[i] = expf(v[i] - mb); s += v[i]; }
#pragma unroll
    for (int o = 16; o > 0; o >>= 1) s += __shfl_xor_sync(0xffffffffu, s, o);
    if ((tid & 31) == 0) red_sum[tid >> 5] = s;
    __syncthreads();
    float tot = 0.0f;
#pragma unroll
    for (int i = 0; i < 8; i++) tot += red_sum[i];
    const float inv = 1.0f / tot;

#pragma unroll
    for (int i = 0; i < 16; i++) row[tid + i * 256] = v[i] * inv;
}

// --- 4) head_out = attn @ V -> g_HO[b,s,h*Dk+k]: grid (2, 32, 8) -----------
__global__ void __launch_bounds__(256) av_kernel(const float* __restrict__ attn_out)
{
    const float* attn = attn_out ? attn_out : g_attn_fallback;
    const int z = blockIdx.z;
    const int h = z >> 1, b = z & 1;
    const float* A = attn + (size_t)z * SEQ * SEQ;
    const float* V = g_V + (size_t)z * SEQ * DK;
    float* C = g_HO + (size_t)b * SEQ * DM + h * DK;
    gemm128x128<false, false>(A, SEQ, V, DK, C, DM, SEQ, 1.0f, nullptr);
}

// --- 5) out = concat @ Wo + bo: grid (8, 64) --------------------------------
__global__ void __launch_bounds__(256) outproj_kernel(
    const float* __restrict__ Wo, const float* __restrict__ bo, float* __restrict__ out)
{
    gemm128x128<false, true>(g_HO, DM, Wo, DM, out, DM, DM, 1.0f, bo);
}

// ---------------------------------------------------------------------------
extern "C" void kernel_launch(void* const* d_in, const int* in_sizes, int n_in,
                              void* d_out, int out_size)
{
    const float* q  = (const float*)d_in[0];
    const float* k  = (const float*)d_in[1];
    const float* v  = (const float*)d_in[2];
    const float* Wq = (const float*)d_in[3];
    const float* bq = (const float*)d_in[4];
    const float* Wk = (const float*)d_in[5];
    const float* bk = (const float*)d_in[6];
    const float* Wv = (const float*)d_in[7];
    const float* bv = (const float*)d_in[8];
    const float* Wo = (const float*)d_in[9];
    const float* bo = (const float*)d_in[10];

    float* out = (float*)d_out;
    const long OUT_ELEMS  = (long)NB * SEQ * DM;          // 8,388,608
    const long ATTN_ELEMS = (long)NH * NB * SEQ * SEQ;    // 134,217,728

    // attn is the second output if d_out is big enough; else use scratch.
    float* attn_out = nullptr;
    if ((long)out_size >= OUT_ELEMS + ATTN_ELEMS) attn_out = out + OUT_ELEMS;

    dim3 blk(256);

    proj_kernel<<<dim3(2, 64, 12), blk>>>(q, k, v, Wq, bq, Wk, bk, Wv, bv);
    scores_kernel<<<dim3(32, 32, 8), blk>>>(attn_out);
    softmax_kernel<<<dim3(NH * NB * SEQ), blk>>>(attn_out);
    av_kernel<<<dim3(2, 32, 8), blk>>>(attn_out);
    outproj_kernel<<<dim3(8, 64, 1), blk>>>(Wo, bo, out);
}

// round 3
// speedup vs baseline: 1.6270x; 1.6270x over previous
#include <cuda_runtime.h>
#include <cstdint>
#include <math.h>

// ---------------------------------------------------------------------------
// LegalMultiHeadAttention — Round 3: tensor cores via portable mma.sync tf32
// (tcgen05 is blocked: harness lowers through compute_103, no 'a' features).
//   B=2, S=4096, D_MODEL=1024, H=4, D_K=256.
// GEMM: 128x128 CTA tile, 8 warps (2x4), warp tile 64x32, m16n8k8 tf32 NT.
// B operand staged either NT-direct (B[n][k]) or transposed in smem (B[k][n]).
// ---------------------------------------------------------------------------

#define SEQ    4096
#define DK     256
#define DM     1024
#define NH     4
#define NB     2
#define BS_TOT (NB*SEQ)          // 8192

// --- device scratch (allocation-free rule) ---
__device__ float g_Q [(size_t)NH*BS_TOT*DK];       // [H*B][S][Dk]
__device__ float g_K [(size_t)NH*BS_TOT*DK];
__device__ float g_V [(size_t)NH*BS_TOT*DK];
__device__ float g_HO[(size_t)BS_TOT*DM];          // [B][S][H*Dk]
__device__ float g_attn_fallback[(size_t)NH*NB*SEQ*SEQ];

__device__ __forceinline__ uint32_t f2tf32(float x) {
    uint32_t u;
    asm("cvt.rna.tf32.f32 %0, %1;" : "=r"(u) : "f"(x));
    return u;
}

__device__ __forceinline__ void mma_tf32(float& c0, float& c1, float& c2, float& c3,
                                         uint32_t a0, uint32_t a1, uint32_t a2, uint32_t a3,
                                         uint32_t b0, uint32_t b1) {
    asm volatile(
        "mma.sync.aligned.m16n8k8.row.col.f32.tf32.tf32.f32 "
        "{%0,%1,%2,%3}, {%4,%5,%6,%7}, {%8,%9}, {%0,%1,%2,%3};"
        : "+f"(c0), "+f"(c1), "+f"(c2), "+f"(c3)
        : "r"(a0), "r"(a1), "r"(a2), "r"(a3), "r"(b0), "r"(b1));
}

#define SPAD 36   // row stride in floats: (4m+k)%32 conflict-free fragment loads

// ---------------------------------------------------------------------------
// Tensor-core tf32 GEMM: C[m,n] = alpha*sum_k A[m,k]*Bop[k,n] (+ bias[n]).
//   BTRANS_STAGE=false: B global is [N][K] row-major (NT direct, ldb = K-stride)
//   BTRANS_STAGE=true:  B global is [K][N] row-major (transposed while staging)
// M,N multiples of 128; K multiple of 32.
// ---------------------------------------------------------------------------
template<bool BTRANS_STAGE, bool HASBIAS>
__device__ void gemm_tc(const float* __restrict__ A, int lda,
                        const float* __restrict__ B, int ldb,
                        float* __restrict__ C, int ldc,
                        int K, float alpha, const float* __restrict__ bias)
{
    __shared__ uint32_t As[128][SPAD];
    __shared__ uint32_t Bs[128][SPAD];

    const int tid  = threadIdx.x;          // 256 threads, 8 warps
    const int wid  = tid >> 5;
    const int lane = tid & 31;
    const int grp  = lane >> 2;            // 0..7
    const int tg   = lane & 3;             // 0..3

    const int wm = (wid & 1) * 64;         // warp M offset in CTA tile
    const int wn = (wid >> 1) * 32;        // warp N offset

    const long bm = (long)blockIdx.y * 128;
    const long bn = (long)blockIdx.x * 128;
    A += bm * (long)lda;
    if (BTRANS_STAGE) B += bn;             // B[k][bn + n]
    else              B += bn * (long)ldb; // B[bn + n][k]

    float acc[4][4][4];
#pragma unroll
    for (int i = 0; i < 4; i++)
#pragma unroll
        for (int j = 0; j < 4; j++)
#pragma unroll
            for (int r = 0; r < 4; r++) acc[i][j][r] = 0.0f;

    // staging indices
    const int arow = tid >> 1;             // A/Bnt: 0..127 (two threads per row)
    const int ac4  = (tid & 1) * 4;        // k/4 offset (x2 float4 below)
    const int bkk  = tid >> 5;             // Btrans: k row base (x4 below)
    const int bn4  = tid & 31;             // Btrans: n/4

    for (int kt = 0; kt < K; kt += 32) {
        // ---- stage A: As[m][k], coalesced float4, tf32-converted ----
#pragma unroll
        for (int h = 0; h < 2; h++) {
            const float4 v = *(const float4*)(A + (long)arow * lda + kt + (ac4 + h * 8) * 4);
            // wait: ac4 is k/4 (0 or 4); elements k = ac4*4 + h*... fix below
            (void)v;
        }
        // (correct staging implemented explicitly:)
        {
            // thread covers rows tid>>1, k-halves (tid&1)*16 .. +16
            const int kbase = (tid & 1) * 16;
#pragma unroll
            for (int h = 0; h < 4; h++) {
                const float4 v = *(const float4*)(A + (long)arow * lda + kt + kbase + h * 4);
                As[arow][kbase + h*4 + 0] = f2tf32(v.x);
                As[arow][kbase + h*4 + 1] = f2tf32(v.y);
                As[arow][kbase + h*4 + 2] = f2tf32(v.z);
                As[arow][kbase + h*4 + 3] = f2tf32(v.w);
            }
        }
        // ---- stage B: Bs[n][k] ----
        if (!BTRANS_STAGE) {
            const int kbase = (tid & 1) * 16;
#pragma unroll
            for (int h = 0; h < 4; h++) {
                const float4 v = *(const float4*)(B + (long)arow * ldb + kt + kbase + h * 4);
                Bs[arow][kbase + h*4 + 0] = f2tf32(v.x);
                Bs[arow][kbase + h*4 + 1] = f2tf32(v.y);
                Bs[arow][kbase + h*4 + 2] = f2tf32(v.z);
                Bs[arow][kbase + h*4 + 3] = f2tf32(v.w);
            }
        } else {
            // B[k][n]: load float4 along n, scatter-transpose to Bs[n][k]
#pragma unroll
            for (int h = 0; h < 4; h++) {
                const int kk = bkk * 4 + h;   // 0..31
                const float4 v = *(const float4*)(B + (long)(kt + kk) * ldb + bn4 * 4);
                Bs[bn4*4 + 0][kk] = f2tf32(v.x);
                Bs[bn4*4 + 1][kk] = f2tf32(v.y);
                Bs[bn4*4 + 2][kk] = f2tf32(v.z);
                Bs[bn4*4 + 3][kk] = f2tf32(v.w);
            }
        }
        __syncthreads();

        // ---- 4 x k8 MMA steps ----
#pragma unroll
        for (int ks = 0; ks < 4; ks++) {
            const int kb = ks * 8;
            uint32_t af[4][4], bf[4][2];
#pragma unroll
            for (int mt = 0; mt < 4; mt++) {
                const int m = wm + mt * 16 + grp;
                af[mt][0] = As[m    ][kb + tg    ];
                af[mt][1] = As[m + 8][kb + tg    ];
                af[mt][2] = As[m    ][kb + tg + 4];
                af[mt][3] = As[m + 8][kb + tg + 4];
            }
#pragma unroll
            for (int nt = 0; nt < 4; nt++) {
                const int n = wn + nt * 8 + grp;
                bf[nt][0] = Bs[n][kb + tg    ];
                bf[nt][1] = Bs[n][kb + tg + 4];
            }
#pragma unroll
            for (int mt = 0; mt < 4; mt++)
#pragma unroll
                for (int nt = 0; nt < 4; nt++)
                    mma_tf32(acc[mt][nt][0], acc[mt][nt][1], acc[mt][nt][2], acc[mt][nt][3],
                             af[mt][0], af[mt][1], af[mt][2], af[mt][3],
                             bf[nt][0], bf[nt][1]);
        }
        __syncthreads();
    }

    // ---- epilogue: c0/c1 at (row, 2tg), c2/c3 at (row+8, 2tg) ----
#pragma unroll
    for (int mt = 0; mt < 4; mt++) {
        const long r0 = bm + wm + mt * 16 + grp;
#pragma unroll
        for (int nt = 0; nt < 4; nt++) {
            const int cn = (int)bn + wn + nt * 8 + 2 * tg;
            float2 v0, v1;
            v0.x = acc[mt][nt][0] * alpha;
            v0.y = acc[mt][nt][1] * alpha;
            v1.x = acc[mt][nt][2] * alpha;
            v1.y = acc[mt][nt][3] * alpha;
            if (HASBIAS) {
                const float b0 = bias[cn], b1 = bias[cn + 1];
                v0.x += b0; v0.y += b1;
                v1.x += b0; v1.y += b1;
            }
            *(float2*)(C + r0 * (long)ldc + cn)       = v0;
            *(float2*)(C + (r0 + 8) * (long)ldc + cn) = v1;
        }
    }
}

// ---------------------------------------------------------------------------
// wrapper kernels
// ---------------------------------------------------------------------------
__global__ void __launch_bounds__(256) proj_tc(
    const float* __restrict__ q, const float* __restrict__ k, const float* __restrict__ v,
    const float* __restrict__ Wq, const float* __restrict__ bq,
    const float* __restrict__ Wk, const float* __restrict__ bk,
    const float* __restrict__ Wv, const float* __restrict__ bv)
{
    const int z = blockIdx.z, mat = z >> 2, head = z & 3;
    const float* A    = mat == 0 ? q  : mat == 1 ? k  : v;
    const float* W    = (mat == 0 ? Wq : mat == 1 ? Wk : Wv) + (size_t)head * DM * DK;
    const float* bias = (mat == 0 ? bq : mat == 1 ? bk : bv) + head * DK;
    float* C = (mat == 0 ? g_Q : mat == 1 ? g_K : g_V) + (size_t)head * BS_TOT * DK;
    gemm_tc<true, true>(A, DM, W, DK, C, DK, DM, 1.0f, bias);   // W is [K][N]
}

__global__ void __launch_bounds__(256) scores_tc(float* __restrict__ attn_out)
{
    float* attn = attn_out ? attn_out : g_attn_fallback;
    const int z = blockIdx.z;
    gemm_tc<false, false>(g_Q + (size_t)z * SEQ * DK, DK,
                          g_K + (size_t)z * SEQ * DK, DK,        // K is [N][K] (NT)
                          attn + (size_t)z * SEQ * SEQ, SEQ, DK, 0.0625f, nullptr);
}

__global__ void __launch_bounds__(256) av_tc(const float* __restrict__ attn_out)
{
    const float* attn = attn_out ? attn_out : g_attn_fallback;
    const int z = blockIdx.z, h = z >> 1, b = z & 1;
    gemm_tc<true, false>(attn + (size_t)z * SEQ * SEQ, SEQ,
                         g_V + (size_t)z * SEQ * DK, DK,         // V is [K][N]
                         g_HO + (size_t)b * SEQ * DM + h * DK, DM, SEQ, 1.0f, nullptr);
}

__global__ void __launch_bounds__(256) outproj_tc(
    const float* __restrict__ Wo, const float* __restrict__ bo, float* __restrict__ out)
{
    gemm_tc<true, true>(g_HO, DM, Wo, DM, out, DM, DM, 1.0f, bo); // Wo is [K][N]
}

// ---------------------------------------------------------------------------
// row softmax in place (attn: 32768 rows x 4096)
// ---------------------------------------------------------------------------
__global__ void __launch_bounds__(256) softmax_kernel(float* __restrict__ attn_out)
{
    float* attn = attn_out ? attn_out : g_attn_fallback;
    float* row = attn + (size_t)blockIdx.x * SEQ;
    const int tid = threadIdx.x;

    float v[16];
    float m = -1e30f;
#pragma unroll
    for (int i = 0; i < 16; i++) { v[i] = row[tid + i * 256]; m = fmaxf(m, v[i]); }

    __shared__ float red_max[8];
    __shared__ float red_sum[8];
#pragma unroll
    for (int o = 16; o > 0; o >>= 1) m = fmaxf(m, __shfl_xor_sync(0xffffffffu, m, o));
    if ((tid & 31) == 0) red_max[tid >> 5] = m;
    __syncthreads();
    float mb = red_max[0];
#pragma unroll
    for (int i = 1; i < 8; i++) mb = fmaxf(mb, red_max[i]);

    float s = 0.0f;
#pragma unroll
    for (int i = 0; i < 16; i++) { v[i] = expf(v[i] - mb); s += v[i]; }
#pragma unroll
    for (int o = 16; o > 0; o >>= 1) s += __shfl_xor_sync(0xffffffffu, s, o);
    if ((tid & 31) == 0) red_sum[tid >> 5] = s;
    __syncthreads();
    float tot = 0.0f;
#pragma unroll
    for (int i = 0; i < 8; i++) tot += red_sum[i];
    const float inv = 1.0f / tot;

#pragma unroll
    for (int i = 0; i < 16; i++) row[tid + i * 256] = v[i] * inv;
}

// ---------------------------------------------------------------------------
extern "C" void kernel_launch(void* const* d_in, const int* in_sizes, int n_in,
                              void* d_out, int out_size)
{
    const float* q  = (const float*)d_in[0];
    const float* k  = (const float*)d_in[1];
    const float* v  = (const float*)d_in[2];
    const float* Wq = (const float*)d_in[3];
    const float* bq = (const float*)d_in[4];
    const float* Wk = (const float*)d_in[5];
    const float* bk = (const float*)d_in[6];
    const float* Wv = (const float*)d_in[7];
    const float* bv = (const float*)d_in[8];
    const float* Wo = (const float*)d_in[9];
    const float* bo = (const float*)d_in[10];

    float* out = (float*)d_out;
    const long OUT_ELEMS  = (long)NB * SEQ * DM;          // 8,388,608
    const long ATTN_ELEMS = (long)NH * NB * SEQ * SEQ;    // 134,217,728
    float* attn_out = nullptr;
    if ((long)out_size >= OUT_ELEMS + ATTN_ELEMS) attn_out = out + OUT_ELEMS;

    proj_tc<<<dim3(2, 64, 12), 256>>>(q, k, v, Wq, bq, Wk, bk, Wv, bv);
    scores_tc<<<dim3(32, 32, 8), 256>>>(attn_out);
    softmax_kernel<<<dim3(NH * NB * SEQ), 256>>>(attn_out);
    av_tc<<<dim3(2, 32, 8), 256>>>(attn_out);
    outproj_tc<<<dim3(8, 64, 1), 256>>>(Wo, bo, out);
}

// round 4
// speedup vs baseline: 3.2258x; 1.9826x over previous
#include <cuda_runtime.h>
#include <cstdint>
#include <math.h>

// ---------------------------------------------------------------------------
// LegalMultiHeadAttention — Round 4: mma.sync tf32 + cp.async double-buffered
// pipeline, 256x128 CTA tile, 8 warps (4x2), 64x64 warp tile, XOR-swizzled
// conflict-free fragment smem layout.
//   B=2, S=4096, D_MODEL=1024, H=4, D_K=256.
// All GEMMs NT: C[m,n] = alpha * sum_k A[m,k]*B[n,k] (+ bias[n]).
// ---------------------------------------------------------------------------

#define SEQ    4096
#define DK     256
#define DM     1024
#define NH     4
#define NB     2
#define BS_TOT (NB*SEQ)          // 8192

// --- device scratch (allocation-free rule) ---
__device__ float g_Q [(size_t)NH*BS_TOT*DK];       // [H*B][S][Dk]
__device__ float g_K [(size_t)NH*BS_TOT*DK];
__device__ float g_V [(size_t)NH*BS_TOT*DK];
__device__ float g_VT[(size_t)NH*BS_TOT*DK];       // [H*B][Dk][S]
__device__ float g_HO[(size_t)BS_TOT*DM];          // [B][S][H*Dk]
__device__ float g_WT[(size_t)3*NH*DK*DM];         // [mat*4+head][Dk][Dm]
__device__ float g_WoT[(size_t)DM*DM];             // [n][k]
__device__ float g_attn_fallback[(size_t)NH*NB*SEQ*SEQ];

__device__ __forceinline__ uint32_t smem_u32(const void* p) {
    uint32_t a;
    asm("{ .reg .u64 t; cvta.to.shared.u64 t, %1; cvt.u32.u64 %0, t; }"
        : "=r"(a) : "l"(p));
    return a;
}
__device__ __forceinline__ uint32_t f2tf32(float x) {
    uint32_t u;
    asm("cvt.rna.tf32.f32 %0, %1;" : "=r"(u) : "f"(x));
    return u;
}
__device__ __forceinline__ void mma_tf32(float& c0, float& c1, float& c2, float& c3,
                                         uint32_t a0, uint32_t a1, uint32_t a2, uint32_t a3,
                                         uint32_t b0, uint32_t b1) {
    asm volatile(
        "mma.sync.aligned.m16n8k8.row.col.f32.tf32.tf32.f32 "
        "{%0,%1,%2,%3}, {%4,%5,%6,%7}, {%8,%9}, {%0,%1,%2,%3};"
        : "+f"(c0), "+f"(c1), "+f"(c2), "+f"(c3)
        : "r"(a0), "r"(a1), "r"(a2), "r"(a3), "r"(b0), "r"(b1));
}
__device__ __forceinline__ void cp16(uint32_t dst, const void* src) {
    asm volatile("cp.async.cg.shared.global [%0], [%1], 16;" :: "r"(dst), "l"(src));
}

// smem word budget: A tile 256x32 = 8192 words, B tile 128x32 = 4096 words.
// double buffered: stride 12288 words (49152 B), total 98304 B.
#define BUF_WORDS 12288
#define SMEM_BYTES (2*BUF_WORDS*4)

// ---------------------------------------------------------------------------
// gemm: CTA 256x128, 8 warps as 4 (M) x 2 (N), warp tile 64x64.
// A layout word: ((((mq*4+mt)*2+i)*8+g)*8 + (kc^g))*4 + tg   (kc = 2ks+j)
// B layout word: (((nh*8+nt)*8+g)*8 + (kc^g))*4 + tg
// ---------------------------------------------------------------------------
template<bool HASBIAS>
__device__ __forceinline__ void gemm_cp(const float* __restrict__ A, int lda,
                                        const float* __restrict__ B, int ldb,
                                        float* __restrict__ C, int ldc,
                                        int K, float alpha, const float* __restrict__ bias)
{
    extern __shared__ float smem[];
    const uint32_t sbase = smem_u32(smem);

    const int tid  = threadIdx.x;           // 256
    const int wid  = tid >> 5;
    const int lane = tid & 31;
    const int grp  = lane >> 2;
    const int tg   = lane & 3;
    const int wm   = (wid >> 1) * 64;       // 0,64,128,192
    const int wn   = (wid & 1) * 64;        // 0,64
    const int mq   = wm >> 6;
    const int nh   = wn >> 6;

    const long bm = (long)blockIdx.y * 256;
    const long bn = (long)blockIdx.x * 128;
    A += bm * (long)lda;
    B += bn * (long)ldb;

    // staging decomposition (per thread, per chunk index)
    // A: idx = c*256+tid, m = idx>>3, kc = idx&7  (8 chunks)
    // B: idx = c*256+tid, n = idx>>3, kc = idx&7  (4 chunks)
    const int sm_  = tid >> 3;               // m (A) / n (B) base row for c=0 step 32
    const int skc  = tid & 7;

    float acc[4][8][4];
#pragma unroll
    for (int i = 0; i < 4; i++)
#pragma unroll
        for (int j = 0; j < 8; j++)
#pragma unroll
            for (int r = 0; r < 4; r++) acc[i][j][r] = 0.0f;

    const int NIT = K >> 5;

    // ---- stage copy macro-ish lambda ----
    auto stage_copy = [&](int stage) {
        const uint32_t db = sbase + (uint32_t)(stage & 1) * (BUF_WORDS * 4);
        const float* Ak = A + stage * 32;
        const float* Bk = B + stage * 32;
#pragma unroll
        for (int c = 0; c < 8; c++) {
            const int m = sm_ + c * 32;
            const int g = m & 7;
            const int chunk = ((((m >> 6) * 4 + ((m >> 4) & 3)) * 2 + ((m >> 3) & 1)) * 8 + g) * 8
                              + (skc ^ g);
            cp16(db + (uint32_t)chunk * 16, Ak + (long)m * lda + skc * 4);
        }
        const uint32_t dbB = db + 8192 * 4;
#pragma unroll
        for (int c = 0; c < 4; c++) {
            const int n = sm_ + c * 32;
            const int g = n & 7;
            const int chunk = (((n >> 6) * 8 + ((n >> 3) & 7)) * 8 + g) * 8 + (skc ^ g);
            cp16(dbB + (uint32_t)chunk * 16, Bk + (long)n * ldb + skc * 4);
        }
        asm volatile("cp.async.commit_group;" ::: "memory");
    };

    stage_copy(0);

#pragma unroll 1
    for (int it = 0; it < NIT; it++) {
        asm volatile("cp.async.wait_group 0;" ::: "memory");
        __syncthreads();
        if (it + 1 < NIT) stage_copy(it + 1);

        const float* sA = smem + (it & 1) * BUF_WORDS;
        const float* sB = sA + 8192;

#pragma unroll
        for (int ks = 0; ks < 4; ks++) {
            uint32_t af[4][4];
#pragma unroll
            for (int mt = 0; mt < 4; mt++) {
                // base row-group for (mq, mt, i, grp)
#pragma unroll
                for (int i = 0; i < 2; i++) {
                    const int rg = (((mq * 4 + mt) * 2 + i) * 8 + grp) * 8;
                    const int w0 = (rg + ((2 * ks + 0) ^ grp)) * 4 + tg;
                    const int w1 = (rg + ((2 * ks + 1) ^ grp)) * 4 + tg;
                    af[mt][i]     = f2tf32(sA[w0]);   // j=0: a0 (i=0), a1 (i=1)
                    af[mt][i + 2] = f2tf32(sA[w1]);   // j=1: a2 (i=0), a3 (i=1)
                }
            }
            uint32_t bf[8][2];
#pragma unroll
            for (int nt = 0; nt < 8; nt++) {
                const int rg = ((nh * 8 + nt) * 8 + grp) * 8;
                bf[nt][0] = f2tf32(sB[(rg + ((2 * ks + 0) ^ grp)) * 4 + tg]);
                bf[nt][1] = f2tf32(sB[(rg + ((2 * ks + 1) ^ grp)) * 4 + tg]);
            }
#pragma unroll
            for (int mt = 0; mt < 4; mt++)
#pragma unroll
                for (int nt = 0; nt < 8; nt++)
                    mma_tf32(acc[mt][nt][0], acc[mt][nt][1], acc[mt][nt][2], acc[mt][nt][3],
                             af[mt][0], af[mt][1], af[mt][2], af[mt][3],
                             bf[nt][0], bf[nt][1]);
        }
        __syncthreads();
    }

    // ---- epilogue ----
#pragma unroll
    for (int mt = 0; mt < 4; mt++) {
        const long r0 = bm + wm + mt * 16 + grp;
#pragma unroll
        for (int nt = 0; nt < 8; nt++) {
            const int cn = (int)bn + wn + nt * 8 + 2 * tg;
            float2 v0, v1;
            v0.x = acc[mt][nt][0] * alpha;
            v0.y = acc[mt][nt][1] * alpha;
            v1.x = acc[mt][nt][2] * alpha;
            v1.y = acc[mt][nt][3] * alpha;
            if (HASBIAS) {
                const float b0 = bias[cn], b1 = bias[cn + 1];
                v0.x += b0; v0.y += b1;
                v1.x += b0; v1.y += b1;
            }
            *(float2*)(C + r0 * (long)ldc + cn)       = v0;
            *(float2*)(C + (r0 + 8) * (long)ldc + cn) = v1;
        }
    }
}

// ---------------------------------------------------------------------------
// transpose kernel: dst[c][r] = src[r][c] per z-slice
//   which 0/1/2: Wq/Wk/Wv [H][R][C] -> g_WT[(which*4+z)][C][R]
//   which 3:     Wo [R][C]          -> g_WoT
//   which 4:     g_V [z][R][C]      -> g_VT[z][C][R]
// ---------------------------------------------------------------------------
__global__ void __launch_bounds__(256) trans_kernel(const float* __restrict__ in,
                                                    int which, int R, int C)
{
    __shared__ float t[32][33];
    const int z = blockIdx.z;
    const float* src;
    float* dst;
    if (which == 4)      { src = g_V + (size_t)z * R * C;  dst = g_VT + (size_t)z * R * C; }
    else if (which == 3) { src = in;                        dst = g_WoT; }
    else                 { src = in + (size_t)z * R * C;    dst = g_WT + ((size_t)which * NH + z) * R * C; }

    const int c0 = blockIdx.x * 32, r0 = blockIdx.y * 32;
    const int tx = threadIdx.x & 31, ty = threadIdx.x >> 5;
#pragma unroll
    for (int i = 0; i < 4; i++)
        t[ty + i * 8][tx] = src[(size_t)(r0 + ty + i * 8) * C + c0 + tx];
    __syncthreads();
#pragma unroll
    for (int i = 0; i < 4; i++)
        dst[(size_t)(c0 + ty + i * 8) * R + r0 + tx] = t[tx][ty + i * 8];
}

// ---------------------------------------------------------------------------
// wrapper kernels
// ---------------------------------------------------------------------------
__global__ void __launch_bounds__(256, 1) proj_tc(
    const float* __restrict__ q, const float* __restrict__ k, const float* __restrict__ v,
    const float* __restrict__ bq, const float* __restrict__ bk, const float* __restrict__ bv)
{
    const int z = blockIdx.z, mat = z >> 2, head = z & 3;
    const float* A    = mat == 0 ? q  : mat == 1 ? k  : v;
    const float* B    = g_WT + (size_t)z * DK * DM;                 // [n=dk][k=dm]
    const float* bias = (mat == 0 ? bq : mat == 1 ? bk : bv) + head * DK;
    float* C = (mat == 0 ? g_Q : mat == 1 ? g_K : g_V) + (size_t)head * BS_TOT * DK;
    gemm_cp<true>(A, DM, B, DM, C, DK, DM, 1.0f, bias);
}

__global__ void __launch_bounds__(256, 1) scores_tc(float* __restrict__ attn_out)
{
    float* attn = attn_out ? attn_out : g_attn_fallback;
    const int z = blockIdx.z;
    gemm_cp<false>(g_Q + (size_t)z * SEQ * DK, DK,
                   g_K + (size_t)z * SEQ * DK, DK,                  // [n=s][k=dk]
                   attn + (size_t)z * SEQ * SEQ, SEQ, DK, 0.0625f, nullptr);
}

__global__ void __launch_bounds__(256, 1) av_tc(const float* __restrict__ attn_out)
{
    const float* attn = attn_out ? attn_out : g_attn_fallback;
    const int z = blockIdx.z, h = z >> 1, b = z & 1;
    gemm_cp<false>(attn + (size_t)z * SEQ * SEQ, SEQ,
                   g_VT + (size_t)z * DK * SEQ, SEQ,                // [n=dk][k=s]
                   g_HO + (size_t)b * SEQ * DM + h * DK, DM, SEQ, 1.0f, nullptr);
}

__global__ void __launch_bounds__(256, 1) outproj_tc(const float* __restrict__ bo,
                                                     float* __restrict__ out)
{
    gemm_cp<true>(g_HO, DM, g_WoT, DM, out, DM, DM, 1.0f, bo);      // [n][k]
}

// ---------------------------------------------------------------------------
// row softmax in place (attn: 32768 rows x 4096)
// ---------------------------------------------------------------------------
__global__ void __launch_bounds__(256) softmax_kernel(float* __restrict__ attn_out)
{
    float* attn = attn_out ? attn_out : g_attn_fallback;
    float* row = attn + (size_t)blockIdx.x * SEQ;
    const int tid = threadIdx.x;

    float v[16];
    float m = -1e30f;
#pragma unroll
    for (int i = 0; i < 16; i++) { v[i] = row[tid + i * 256]; m = fmaxf(m, v[i]); }

    __shared__ float red_max[8];
    __shared__ float red_sum[8];
#pragma unroll
    for (int o = 16; o > 0; o >>= 1) m = fmaxf(m, __shfl_xor_sync(0xffffffffu, m, o));
    if ((tid & 31) == 0) red_max[tid >> 5] = m;
    __syncthreads();
    float mb = red_max[0];
#pragma unroll
    for (int i = 1; i < 8; i++) mb = fmaxf(mb, red_max[i]);

    float s = 0.0f;
#pragma unroll
    for (int i = 0; i < 16; i++) { v[i] = expf(v[i] - mb); s += v[i]; }
#pragma unroll
    for (int o = 16; o > 0; o >>= 1) s += __shfl_xor_sync(0xffffffffu, s, o);
    if ((tid & 31) == 0) red_sum[tid >> 5] = s;
    __syncthreads();
    float tot = 0.0f;
#pragma unroll
    for (int i = 0; i < 8; i++) tot += red_sum[i];
    const float inv = 1.0f / tot;

#pragma unroll
    for (int i = 0; i < 16; i++) row[tid + i * 256] = v[i] * inv;
}

// ---------------------------------------------------------------------------
extern "C" void kernel_launch(void* const* d_in, const int* in_sizes, int n_in,
                              void* d_out, int out_size)
{
    const float* q  = (const float*)d_in[0];
    const float* k  = (const float*)d_in[1];
    const float* v  = (const float*)d_in[2];
    const float* Wq = (const float*)d_in[3];
    const float* bq = (const float*)d_in[4];
    const float* Wk = (const float*)d_in[5];
    const float* bk = (const float*)d_in[6];
    const float* Wv = (const float*)d_in[7];
    const float* bv = (const float*)d_in[8];
    const float* Wo = (const float*)d_in[9];
    const float* bo = (const float*)d_in[10];

    float* out = (float*)d_out;
    const long OUT_ELEMS  = (long)NB * SEQ * DM;          // 8,388,608
    const long ATTN_ELEMS = (long)NH * NB * SEQ * SEQ;    // 134,217,728
    float* attn_out = nullptr;
    if ((long)out_size >= OUT_ELEMS + ATTN_ELEMS) attn_out = out + OUT_ELEMS;

    cudaFuncSetAttribute(proj_tc,    cudaFuncAttributeMaxDynamicSharedMemorySize, SMEM_BYTES);
    cudaFuncSetAttribute(scores_tc,  cudaFuncAttributeMaxDynamicSharedMemorySize, SMEM_BYTES);
    cudaFuncSetAttribute(av_tc,      cudaFuncAttributeMaxDynamicSharedMemorySize, SMEM_BYTES);
    cudaFuncSetAttribute(outproj_tc, cudaFuncAttributeMaxDynamicSharedMemorySize, SMEM_BYTES);

    // weight transposes -> [n][k] operands
    trans_kernel<<<dim3(8, 32, 4),  256>>>(Wq, 0, DM, DK);
    trans_kernel<<<dim3(8, 32, 4),  256>>>(Wk, 1, DM, DK);
    trans_kernel<<<dim3(8, 32, 4),  256>>>(Wv, 2, DM, DK);
    trans_kernel<<<dim3(32, 32, 1), 256>>>(Wo, 3, DM, DM);

    // Q/K/V projections: M=8192 (grid.y=32), N=256 (grid.x=2)
    proj_tc<<<dim3(2, 32, 12), 256, SMEM_BYTES>>>(q, k, v, bq, bk, bv);

    // V -> V^T
    trans_kernel<<<dim3(8, 128, 8), 256>>>(nullptr, 4, SEQ, DK);

    // scores: M=4096 (16), N=4096 (32), z=8
    scores_tc<<<dim3(32, 16, 8), 256, SMEM_BYTES>>>(attn_out);

    // softmax
    softmax_kernel<<<dim3(NH * NB * SEQ), 256>>>(attn_out);

    // head_out = attn @ V: M=4096 (16), N=256 (2), z=8
    av_tc<<<dim3(2, 16, 8), 256, SMEM_BYTES>>>(attn_out);

    // out = concat @ Wo + bo: M=8192 (32), N=1024 (8)
    outproj_tc<<<dim3(8, 32, 1), 256, SMEM_BYTES>>>(bo, out);
}

// round 5
// speedup vs baseline: 3.2469x; 1.0065x over previous
#include <cuda_runtime.h>
#include <cstdint>
#include <math.h>

// ---------------------------------------------------------------------------
// LegalMultiHeadAttention — Round 5: templated warp-grid mma.sync tf32 GEMM
// (cp.async double-buffered, XOR-swizzled smem). av/proj/outproj use 128x256
// tiles (grid.x=1 => A read once); scores keeps 256x128. Softmax: float4+expf.
//   B=2, S=4096, D_MODEL=1024, H=4, D_K=256.
// ---------------------------------------------------------------------------

#define SEQ    4096
#define DK     256
#define DM     1024
#define NH     4
#define NB     2
#define BS_TOT (NB*SEQ)          // 8192

__device__ float g_Q [(size_t)NH*BS_TOT*DK];
__device__ float g_K [(size_t)NH*BS_TOT*DK];
__device__ float g_V [(size_t)NH*BS_TOT*DK];
__device__ float g_VT[(size_t)NH*BS_TOT*DK];
__device__ float g_HO[(size_t)BS_TOT*DM];
__device__ float g_WT[(size_t)3*NH*DK*DM];
__device__ float g_WoT[(size_t)DM*DM];
__device__ float g_attn_fallback[(size_t)NH*NB*SEQ*SEQ];

__device__ __forceinline__ uint32_t smem_u32(const void* p) {
    uint32_t a;
    asm("{ .reg .u64 t; cvta.to.shared.u64 t, %1; cvt.u32.u64 %0, t; }"
        : "=r"(a) : "l"(p));
    return a;
}
__device__ __forceinline__ uint32_t f2tf32(float x) {
    uint32_t u;
    asm("cvt.rna.tf32.f32 %0, %1;" : "=r"(u) : "f"(x));
    return u;
}
__device__ __forceinline__ void mma_tf32(float& c0, float& c1, float& c2, float& c3,
                                         uint32_t a0, uint32_t a1, uint32_t a2, uint32_t a3,
                                         uint32_t b0, uint32_t b1) {
    asm volatile(
        "mma.sync.aligned.m16n8k8.row.col.f32.tf32.tf32.f32 "
        "{%0,%1,%2,%3}, {%4,%5,%6,%7}, {%8,%9}, {%0,%1,%2,%3};"
        : "+f"(c0), "+f"(c1), "+f"(c2), "+f"(c3)
        : "r"(a0), "r"(a1), "r"(a2), "r"(a3), "r"(b0), "r"(b1));
}
__device__ __forceinline__ void cp16(uint32_t dst, const void* src) {
    asm volatile("cp.async.cg.shared.global [%0], [%1], 16;" :: "r"(dst), "l"(src));
}

// per-stage words: (WGM+WGN)*2048 = 12288 for all 8-warp configs used here
#define BUF_WORDS 12288
#define SMEM_BYTES (2*BUF_WORDS*4)     // 98304

// ---------------------------------------------------------------------------
// GEMM: CTA tile (WGM*64) x (WGN*64), 8 warps as WGM x WGN, warp tile 64x64.
// NT: C[m,n] = alpha * sum_k A[m,k]*B[n,k] (+ bias[n]).
// smem word layout per tile: ((row>>3)*64 + (row&7)*8 + (kc^(row&7)))*4 + tg
// ---------------------------------------------------------------------------
template<int WGM, int WGN, bool HASBIAS>
__device__ __forceinline__ void gemm_cp(const float* __restrict__ A, int lda,
                                        const float* __restrict__ B, int ldb,
                                        float* __restrict__ C, int ldc,
                                        int K, float alpha, const float* __restrict__ bias)
{
    extern __shared__ float smem[];
    const uint32_t sbase = smem_u32(smem);

    const int tid  = threadIdx.x;           // 256
    const int wid  = tid >> 5;
    const int lane = tid & 31;
    const int grp  = lane >> 2;
    const int tg   = lane & 3;
    const int wm   = (wid / WGN) * 64;
    const int wn   = (wid % WGN) * 64;

    const long bm = (long)blockIdx.y * (WGM * 64);
    const long bn = (long)blockIdx.x * (WGN * 64);
    A += bm * (long)lda;
    B += bn * (long)ldb;

    const int sm_ = tid >> 3;                // 0..31
    const int skc = tid & 7;

    float acc[4][8][4];
#pragma unroll
    for (int i = 0; i < 4; i++)
#pragma unroll
        for (int j = 0; j < 8; j++)
#pragma unroll
            for (int r = 0; r < 4; r++) acc[i][j][r] = 0.0f;

    const int NIT = K >> 5;
    const int AWORDS = WGM * 2048;

    auto stage_copy = [&](int stage) {
        const uint32_t db = sbase + (uint32_t)(stage & 1) * (BUF_WORDS * 4);
        const float* Ak = A + stage * 32;
        const float* Bk = B + stage * 32;
#pragma unroll
        for (int c = 0; c < 2 * WGM; c++) {
            const int m = sm_ + c * 32;
            const int g = m & 7;
            const int chunk = (m >> 3) * 64 + g * 8 + (skc ^ g);
            cp16(db + (uint32_t)chunk * 16, Ak + (long)m * lda + skc * 4);
        }
        const uint32_t dbB = db + (uint32_t)AWORDS * 4;
#pragma unroll
        for (int c = 0; c < 2 * WGN; c++) {
            const int n = sm_ + c * 32;
            const int g = n & 7;
            const int chunk = (n >> 3) * 64 + g * 8 + (skc ^ g);
            cp16(dbB + (uint32_t)chunk * 16, Bk + (long)n * ldb + skc * 4);
        }
        asm volatile("cp.async.commit_group;" ::: "memory");
    };

    stage_copy(0);

#pragma unroll 1
    for (int it = 0; it < NIT; it++) {
        asm volatile("cp.async.wait_group 0;" ::: "memory");
        __syncthreads();
        if (it + 1 < NIT) stage_copy(it + 1);

        const float* sA = smem + (it & 1) * BUF_WORDS;
        const float* sB = sA + AWORDS;

#pragma unroll
        for (int ks = 0; ks < 4; ks++) {
            uint32_t af[4][4];
#pragma unroll
            for (int mt = 0; mt < 4; mt++) {
#pragma unroll
                for (int i = 0; i < 2; i++) {
                    const int rg8 = ((wm >> 3) + mt * 2 + i);
                    const int base = rg8 * 64 + grp * 8;
                    af[mt][i]     = f2tf32(sA[(base + ((2 * ks + 0) ^ grp)) * 4 + tg]);
                    af[mt][i + 2] = f2tf32(sA[(base + ((2 * ks + 1) ^ grp)) * 4 + tg]);
                }
            }
            uint32_t bf[8][2];
#pragma unroll
            for (int nt = 0; nt < 8; nt++) {
                const int base = ((wn >> 3) + nt) * 64 + grp * 8;
                bf[nt][0] = f2tf32(sB[(base + ((2 * ks + 0) ^ grp)) * 4 + tg]);
                bf[nt][1] = f2tf32(sB[(base + ((2 * ks + 1) ^ grp)) * 4 + tg]);
            }
#pragma unroll
            for (int mt = 0; mt < 4; mt++)
#pragma unroll
                for (int nt = 0; nt < 8; nt++)
                    mma_tf32(acc[mt][nt][0], acc[mt][nt][1], acc[mt][nt][2], acc[mt][nt][3],
                             af[mt][0], af[mt][1], af[mt][2], af[mt][3],
                             bf[nt][0], bf[nt][1]);
        }
        __syncthreads();
    }

#pragma unroll
    for (int mt = 0; mt < 4; mt++) {
        const long r0 = bm + wm + mt * 16 + grp;
#pragma unroll
        for (int nt = 0; nt < 8; nt++) {
            const int cn = (int)bn + wn + nt * 8 + 2 * tg;
            float2 v0, v1;
            v0.x = acc[mt][nt][0] * alpha;
            v0.y = acc[mt][nt][1] * alpha;
            v1.x = acc[mt][nt][2] * alpha;
            v1.y = acc[mt][nt][3] * alpha;
            if (HASBIAS) {
                const float b0 = bias[cn], b1 = bias[cn + 1];
                v0.x += b0; v0.y += b1;
                v1.x += b0; v1.y += b1;
            }
            *(float2*)(C + r0 * (long)ldc + cn)       = v0;
            *(float2*)(C + (r0 + 8) * (long)ldc + cn) = v1;
        }
    }
}

// ---------------------------------------------------------------------------
__global__ void __launch_bounds__(256) trans_kernel(const float* __restrict__ in,
                                                    int which, int R, int C)
{
    __shared__ float t[32][33];
    const int z = blockIdx.z;
    const float* src;
    float* dst;
    if (which == 4)      { src = g_V + (size_t)z * R * C;  dst = g_VT + (size_t)z * R * C; }
    else if (which == 3) { src = in;                        dst = g_WoT; }
    else                 { src = in + (size_t)z * R * C;    dst = g_WT + ((size_t)which * NH + z) * R * C; }

    const int c0 = blockIdx.x * 32, r0 = blockIdx.y * 32;
    const int tx = threadIdx.x & 31, ty = threadIdx.x >> 5;
#pragma unroll
    for (int i = 0; i < 4; i++)
        t[ty + i * 8][tx] = src[(size_t)(r0 + ty + i * 8) * C + c0 + tx];
    __syncthreads();
#pragma unroll
    for (int i = 0; i < 4; i++)
        dst[(size_t)(c0 + ty + i * 8) * R + r0 + tx] = t[tx][ty + i * 8];
}

// ---------------------------------------------------------------------------
__global__ void __launch_bounds__(256, 1) proj_tc(
    const float* __restrict__ q, const float* __restrict__ k, const float* __restrict__ v,
    const float* __restrict__ bq, const float* __restrict__ bk, const float* __restrict__ bv)
{
    const int z = blockIdx.z, mat = z >> 2, head = z & 3;
    const float* A    = mat == 0 ? q  : mat == 1 ? k  : v;
    const float* B    = g_WT + (size_t)z * DK * DM;
    const float* bias = (mat == 0 ? bq : mat == 1 ? bk : bv) + head * DK;
    float* C = (mat == 0 ? g_Q : mat == 1 ? g_K : g_V) + (size_t)head * BS_TOT * DK;
    gemm_cp<2, 4, true>(A, DM, B, DM, C, DK, DM, 1.0f, bias);    // 128x256 tile
}

__global__ void __launch_bounds__(256, 1) scores_tc(float* __restrict__ attn_out)
{
    float* attn = attn_out ? attn_out : g_attn_fallback;
    const int z = blockIdx.z;
    gemm_cp<4, 2, false>(g_Q + (size_t)z * SEQ * DK, DK,
                         g_K + (size_t)z * SEQ * DK, DK,
                         attn + (size_t)z * SEQ * SEQ, SEQ, DK, 0.0625f, nullptr);
}

__global__ void __launch_bounds__(256, 1) av_tc(const float* __restrict__ attn_out)
{
    const float* attn = attn_out ? attn_out : g_attn_fallback;
    const int z = blockIdx.z, h = z >> 1, b = z & 1;
    gemm_cp<2, 4, false>(attn + (size_t)z * SEQ * SEQ, SEQ,
                         g_VT + (size_t)z * DK * SEQ, SEQ,
                         g_HO + (size_t)b * SEQ * DM + h * DK, DM, SEQ, 1.0f, nullptr);
}

__global__ void __launch_bounds__(256, 1) outproj_tc(const float* __restrict__ bo,
                                                     float* __restrict__ out)
{
    gemm_cp<2, 4, true>(g_HO, DM, g_WoT, DM, out, DM, DM, 1.0f, bo);
}

// ---------------------------------------------------------------------------
// row softmax in place: float4 I/O, __expf
// ---------------------------------------------------------------------------
__global__ void __launch_bounds__(256) softmax_kernel(float* __restrict__ attn_out)
{
    float* attn = attn_out ? attn_out : g_attn_fallback;
    float4* row = (float4*)(attn + (size_t)blockIdx.x * SEQ);
    const int tid = threadIdx.x;

    float4 v[4];
    float m = -1e30f;
#pragma unroll
    for (int i = 0; i < 4; i++) {
        v[i] = row[tid + i * 256];
        m = fmaxf(m, fmaxf(fmaxf(v[i].x, v[i].y), fmaxf(v[i].z, v[i].w)));
    }

    __shared__ float red_max[8];
    __shared__ float red_sum[8];
#pragma unroll
    for (int o = 16; o > 0; o >>= 1) m = fmaxf(m, __shfl_xor_sync(0xffffffffu, m, o));
    if ((tid & 31) == 0) red_max[tid >> 5] = m;
    __syncthreads();
    float mb = red_max[0];
#pragma unroll
    for (int i = 1; i < 8; i++) mb = fmaxf(mb, red_max[i]);

    float s = 0.0f;
#pragma unroll
    for (int i = 0; i < 4; i++) {
        v[i].x = __expf(v[i].x - mb); v[i].y = __expf(v[i].y - mb);
        v[i].z = __expf(v[i].z - mb); v[i].w = __expf(v[i].w - mb);
        s += (v[i].x + v[i].y) + (v[i].z + v[i].w);
    }
#pragma unroll
    for (int o = 16; o > 0; o >>= 1) s += __shfl_xor_sync(0xffffffffu, s, o);
    if ((tid & 31) == 0) red_sum[tid >> 5] = s;
    __syncthreads();
    float tot = 0.0f;
#pragma unroll
    for (int i = 0; i < 8; i++) tot += red_sum[i];
    const float inv = 1.0f / tot;

#pragma unroll
    for (int i = 0; i < 4; i++) {
        v[i].x *= inv; v[i].y *= inv; v[i].z *= inv; v[i].w *= inv;
        row[tid + i * 256] = v[i];
    }
}

// ---------------------------------------------------------------------------
extern "C" void kernel_launch(void* const* d_in, const int* in_sizes, int n_in,
                              void* d_out, int out_size)
{
    const float* q  = (const float*)d_in[0];
    const float* k  = (const float*)d_in[1];
    const float* v  = (const float*)d_in[2];
    const float* Wq = (const float*)d_in[3];
    const float* bq = (const float*)d_in[4];
    const float* Wk = (const float*)d_in[5];
    const float* bk = (const float*)d_in[6];
    const float* Wv = (const float*)d_in[7];
    const float* bv = (const float*)d_in[8];
    const float* Wo = (const float*)d_in[9];
    const float* bo = (const float*)d_in[10];

    float* out = (float*)d_out;
    const long OUT_ELEMS  = (long)NB * SEQ * DM;
    const long ATTN_ELEMS = (long)NH * NB * SEQ * SEQ;
    float* attn_out = nullptr;
    if ((long)out_size >= OUT_ELEMS + ATTN_ELEMS) attn_out = out + OUT_ELEMS;

    cudaFuncSetAttribute(proj_tc,    cudaFuncAttributeMaxDynamicSharedMemorySize, SMEM_BYTES);
    cudaFuncSetAttribute(scores_tc,  cudaFuncAttributeMaxDynamicSharedMemorySize, SMEM_BYTES);
    cudaFuncSetAttribute(av_tc,      cudaFuncAttributeMaxDynamicSharedMemorySize, SMEM_BYTES);
    cudaFuncSetAttribute(outproj_tc, cudaFuncAttributeMaxDynamicSharedMemorySize, SMEM_BYTES);

    trans_kernel<<<dim3(8, 32, 4),  256>>>(Wq, 0, DM, DK);
    trans_kernel<<<dim3(8, 32, 4),  256>>>(Wk, 1, DM, DK);
    trans_kernel<<<dim3(8, 32, 4),  256>>>(Wv, 2, DM, DK);
    trans_kernel<<<dim3(32, 32, 1), 256>>>(Wo, 3, DM, DM);

    // proj: 128x256 tiles -> grid (1, 64, 12); A read once
    proj_tc<<<dim3(1, 64, 12), 256, SMEM_BYTES>>>(q, k, v, bq, bk, bv);

    trans_kernel<<<dim3(8, 128, 8), 256>>>(nullptr, 4, SEQ, DK);

    // scores: 256x128 tiles -> grid (32, 16, 8)
    scores_tc<<<dim3(32, 16, 8), 256, SMEM_BYTES>>>(attn_out);

    softmax_kernel<<<dim3(NH * NB * SEQ), 256>>>(attn_out);

    // av: 128x256 tiles -> grid (1, 32, 8); attn read once
    av_tc<<<dim3(1, 32, 8), 256, SMEM_BYTES>>>(attn_out);

    // outproj: 128x256 tiles -> grid (4, 64)
    outproj_tc<<<dim3(4, 64, 1), 256, SMEM_BYTES>>>(bo, out);
}

// round 6
// speedup vs baseline: 3.5139x; 1.0822x over previous
#include <cuda_runtime.h>
#include <cstdint>
#include <math.h>

// ---------------------------------------------------------------------------
// LegalMultiHeadAttention — Round 6: 3-stage cp.async pipeline, 1 sync/stage,
// tf32 conversion hoisted to producers (inner loop = LDS -> MMA only).
//   B=2, S=4096, D_MODEL=1024, H=4, D_K=256.
// GEMM: CTA (WGM*64)x(WGN*64), 8 warps, warp tile 64x64, mma m16n8k8 tf32 NT.
// ---------------------------------------------------------------------------

#define SEQ    4096
#define DK     256
#define DM     1024
#define NH     4
#define NB     2
#define BS_TOT (NB*SEQ)          // 8192

__device__ float g_Q [(size_t)NH*BS_TOT*DK];   // tf32-rounded
__device__ float g_K [(size_t)NH*BS_TOT*DK];   // tf32-rounded
__device__ float g_V [(size_t)NH*BS_TOT*DK];   // tf32-rounded
__device__ float g_VT[(size_t)NH*BS_TOT*DK];   // tf32-rounded
__device__ float g_HO[(size_t)BS_TOT*DM];      // tf32-rounded
__device__ float g_WT[(size_t)3*NH*DK*DM];     // tf32-rounded
__device__ float g_WoT[(size_t)DM*DM];         // tf32-rounded
__device__ float g_attn_fallback[(size_t)NH*NB*SEQ*SEQ];

__device__ __forceinline__ uint32_t smem_u32(const void* p) {
    uint32_t a;
    asm("{ .reg .u64 t; cvta.to.shared.u64 t, %1; cvt.u32.u64 %0, t; }"
        : "=r"(a) : "l"(p));
    return a;
}
__device__ __forceinline__ uint32_t f2tf32(float x) {
    uint32_t u;
    asm("cvt.rna.tf32.f32 %0, %1;" : "=r"(u) : "f"(x));
    return u;
}
__device__ __forceinline__ float roundtf(float x) { return __uint_as_float(f2tf32(x)); }

__device__ __forceinline__ void mma_tf32(float& c0, float& c1, float& c2, float& c3,
                                         uint32_t a0, uint32_t a1, uint32_t a2, uint32_t a3,
                                         uint32_t b0, uint32_t b1) {
    asm volatile(
        "mma.sync.aligned.m16n8k8.row.col.f32.tf32.tf32.f32 "
        "{%0,%1,%2,%3}, {%4,%5,%6,%7}, {%8,%9}, {%0,%1,%2,%3};"
        : "+f"(c0), "+f"(c1), "+f"(c2), "+f"(c3)
        : "r"(a0), "r"(a1), "r"(a2), "r"(a3), "r"(b0), "r"(b1));
}
__device__ __forceinline__ void cp16(uint32_t dst, const void* src) {
    asm volatile("cp.async.cg.shared.global [%0], [%1], 16;" :: "r"(dst), "l"(src));
}

#define NSTAGE 3
#define BUF_WORDS 12288                      // (WGM+WGN)*2048 = 12288 (all configs)
#define SMEM_BYTES (NSTAGE*BUF_WORDS*4)      // 147456

// ---------------------------------------------------------------------------
// GEMM NT: C[m,n] = alpha*sum_k A[m,k]*B[n,k] (+bias[n]).
// smem word layout per tile: ((row>>3)*64 + (row&7)*8 + (kc^(row&7)))*4 + tg
// CVTA/CVTB: convert fragment to tf32 on load (operand not pre-rounded).
// ROUND_OUT: tf32-round C before store (C feeds a later GEMM without cvt).
// ---------------------------------------------------------------------------
template<int WGM, int WGN, bool CVTA, bool HASBIAS, bool ROUND_OUT>
__device__ __forceinline__ void gemm_cp(const float* __restrict__ A, int lda,
                                        const float* __restrict__ B, int ldb,
                                        float* __restrict__ C, int ldc,
                                        int K, float alpha, const float* __restrict__ bias)
{
    extern __shared__ float smem[];
    const uint32_t sbase = smem_u32(smem);

    const int tid  = threadIdx.x;           // 256
    const int wid  = tid >> 5;
    const int lane = tid & 31;
    const int grp  = lane >> 2;
    const int tg   = lane & 3;
    const int wm   = (wid / WGN) * 64;
    const int wn   = (wid % WGN) * 64;

    const long bm = (long)blockIdx.y * (WGM * 64);
    const long bn = (long)blockIdx.x * (WGN * 64);
    A += bm * (long)lda;
    B += bn * (long)ldb;

    const int sm_ = tid >> 3;
    const int skc = tid & 7;

    float acc[4][8][4];
#pragma unroll
    for (int i = 0; i < 4; i++)
#pragma unroll
        for (int j = 0; j < 8; j++)
#pragma unroll
            for (int r = 0; r < 4; r++) acc[i][j][r] = 0.0f;

    const int NIT = K >> 5;
    const int AWORDS = WGM * 2048;

    auto stage_copy = [&](int stage, int buf) {
        const uint32_t db = sbase + (uint32_t)buf * (BUF_WORDS * 4);
        const float* Ak = A + stage * 32;
        const float* Bk = B + stage * 32;
#pragma unroll
        for (int c = 0; c < 2 * WGM; c++) {
            const int m = sm_ + c * 32;
            const int g = m & 7;
            const int chunk = (m >> 3) * 64 + g * 8 + (skc ^ g);
            cp16(db + (uint32_t)chunk * 16, Ak + (long)m * lda + skc * 4);
        }
        const uint32_t dbB = db + (uint32_t)AWORDS * 4;
#pragma unroll
        for (int c = 0; c < 2 * WGN; c++) {
            const int n = sm_ + c * 32;
            const int g = n & 7;
            const int chunk = (n >> 3) * 64 + g * 8 + (skc ^ g);
            cp16(dbB + (uint32_t)chunk * 16, Bk + (long)n * ldb + skc * 4);
        }
        asm volatile("cp.async.commit_group;" ::: "memory");
    };

    stage_copy(0, 0);
    stage_copy(1, 1);

    int cbuf = 0;
#pragma unroll 1
    for (int it = 0; it < NIT; it++) {
        asm volatile("cp.async.wait_group %0;" :: "n"(NSTAGE - 2) : "memory");
        __syncthreads();
        if (it + 2 < NIT) {
            int nb = cbuf + 2; if (nb >= NSTAGE) nb -= NSTAGE;
            stage_copy(it + 2, nb);
        }

        const float* sA = smem + cbuf * BUF_WORDS;
        const float* sB = sA + AWORDS;

#pragma unroll
        for (int ks = 0; ks < 4; ks++) {
            uint32_t af[4][4];
#pragma unroll
            for (int mt = 0; mt < 4; mt++) {
#pragma unroll
                for (int i = 0; i < 2; i++) {
                    const int base = ((wm >> 3) + mt * 2 + i) * 64 + grp * 8;
                    const float v0 = sA[(base + ((2 * ks + 0) ^ grp)) * 4 + tg];
                    const float v1 = sA[(base + ((2 * ks + 1) ^ grp)) * 4 + tg];
                    af[mt][i]     = CVTA ? f2tf32(v0) : __float_as_uint(v0);
                    af[mt][i + 2] = CVTA ? f2tf32(v1) : __float_as_uint(v1);
                }
            }
            uint32_t bf[8][2];
#pragma unroll
            for (int nt = 0; nt < 8; nt++) {
                const int base = ((wn >> 3) + nt) * 64 + grp * 8;
                bf[nt][0] = __float_as_uint(sB[(base + ((2 * ks + 0) ^ grp)) * 4 + tg]);
                bf[nt][1] = __float_as_uint(sB[(base + ((2 * ks + 1) ^ grp)) * 4 + tg]);
            }
#pragma unroll
            for (int mt = 0; mt < 4; mt++)
#pragma unroll
                for (int nt = 0; nt < 8; nt++)
                    mma_tf32(acc[mt][nt][0], acc[mt][nt][1], acc[mt][nt][2], acc[mt][nt][3],
                             af[mt][0], af[mt][1], af[mt][2], af[mt][3],
                             bf[nt][0], bf[nt][1]);
        }
        cbuf++; if (cbuf >= NSTAGE) cbuf = 0;
    }

#pragma unroll
    for (int mt = 0; mt < 4; mt++) {
        const long r0 = bm + wm + mt * 16 + grp;
#pragma unroll
        for (int nt = 0; nt < 8; nt++) {
            const int cn = (int)bn + wn + nt * 8 + 2 * tg;
            float2 v0, v1;
            v0.x = acc[mt][nt][0] * alpha;
            v0.y = acc[mt][nt][1] * alpha;
            v1.x = acc[mt][nt][2] * alpha;
            v1.y = acc[mt][nt][3] * alpha;
            if (HASBIAS) {
                const float b0 = bias[cn], b1 = bias[cn + 1];
                v0.x += b0; v0.y += b1;
                v1.x += b0; v1.y += b1;
            }
            if (ROUND_OUT) {
                v0.x = roundtf(v0.x); v0.y = roundtf(v0.y);
                v1.x = roundtf(v1.x); v1.y = roundtf(v1.y);
            }
            *(float2*)(C + r0 * (long)ldc + cn)       = v0;
            *(float2*)(C + (r0 + 8) * (long)ldc + cn) = v1;
        }
    }
}

// ---------------------------------------------------------------------------
// transpose (+tf32 round): dst[c][r] = round(src[r][c])
// ---------------------------------------------------------------------------
__global__ void __launch_bounds__(256) trans_kernel(const float* __restrict__ in,
                                                    int which, int R, int C)
{
    __shared__ float t[32][33];
    const int z = blockIdx.z;
    const float* src;
    float* dst;
    if (which == 4)      { src = g_V + (size_t)z * R * C;  dst = g_VT + (size_t)z * R * C; }
    else if (which == 3) { src = in;                        dst = g_WoT; }
    else                 { src = in + (size_t)z * R * C;    dst = g_WT + ((size_t)which * NH + z) * R * C; }

    const int c0 = blockIdx.x * 32, r0 = blockIdx.y * 32;
    const int tx = threadIdx.x & 31, ty = threadIdx.x >> 5;
#pragma unroll
    for (int i = 0; i < 4; i++)
        t[ty + i * 8][tx] = roundtf(src[(size_t)(r0 + ty + i * 8) * C + c0 + tx]);
    __syncthreads();
#pragma unroll
    for (int i = 0; i < 4; i++)
        dst[(size_t)(c0 + ty + i * 8) * R + r0 + tx] = t[tx][ty + i * 8];
}

// ---------------------------------------------------------------------------
__global__ void __launch_bounds__(256, 1) proj_tc(
    const float* __restrict__ q, const float* __restrict__ k, const float* __restrict__ v,
    const float* __restrict__ bq, const float* __restrict__ bk, const float* __restrict__ bv)
{
    const int z = blockIdx.z, mat = z >> 2, head = z & 3;
    const float* A    = mat == 0 ? q  : mat == 1 ? k  : v;
    const float* B    = g_WT + (size_t)z * DK * DM;
    const float* bias = (mat == 0 ? bq : mat == 1 ? bk : bv) + head * DK;
    float* C = (mat == 0 ? g_Q : mat == 1 ? g_K : g_V) + (size_t)head * BS_TOT * DK;
    // A raw fp32 -> CVTA; output rounded (feeds scores / VT without cvt)
    gemm_cp<2, 4, true, true, true>(A, DM, B, DM, C, DK, DM, 1.0f, bias);
}

__global__ void __launch_bounds__(256, 1) scores_tc(float* __restrict__ attn_out)
{
    float* attn = attn_out ? attn_out : g_attn_fallback;
    const int z = blockIdx.z;
    // Q,K pre-rounded -> no cvt; output stays fp32 (feeds exp)
    gemm_cp<4, 2, false, false, false>(g_Q + (size_t)z * SEQ * DK, DK,
                                       g_K + (size_t)z * SEQ * DK, DK,
                                       attn + (size_t)z * SEQ * SEQ, SEQ, DK, 0.0625f, nullptr);
}

__global__ void __launch_bounds__(256, 1) av_tc(const float* __restrict__ attn_out)
{
    const float* attn = attn_out ? attn_out : g_attn_fallback;
    const int z = blockIdx.z, h = z >> 1, b = z & 1;
    // attn fp32 (output tensor) -> CVTA; HO rounded (feeds outproj)
    gemm_cp<2, 4, true, false, true>(attn + (size_t)z * SEQ * SEQ, SEQ,
                                     g_VT + (size_t)z * DK * SEQ, SEQ,
                                     g_HO + (size_t)b * SEQ * DM + h * DK, DM, SEQ, 1.0f, nullptr);
}

__global__ void __launch_bounds__(256, 1) outproj_tc(const float* __restrict__ bo,
                                                     float* __restrict__ out)
{
    // HO, WoT pre-rounded -> no cvt; final output fp32
    gemm_cp<2, 4, false, true, false>(g_HO, DM, g_WoT, DM, out, DM, DM, 1.0f, bo);
}

// ---------------------------------------------------------------------------
// row softmax in place: float4 I/O, __expf
// ---------------------------------------------------------------------------
__global__ void __launch_bounds__(256) softmax_kernel(float* __restrict__ attn_out)
{
    float* attn = attn_out ? attn_out : g_attn_fallback;
    float4* row = (float4*)(attn + (size_t)blockIdx.x * SEQ);
    const int tid = threadIdx.x;

    float4 v[4];
    float m = -1e30f;
#pragma unroll
    for (int i = 0; i < 4; i++) {
        v[i] = row[tid + i * 256];
        m = fmaxf(m, fmaxf(fmaxf(v[i].x, v[i].y), fmaxf(v[i].z, v[i].w)));
    }

    __shared__ float red_max[8];
    __shared__ float red_sum[8];
#pragma unroll
    for (int o = 16; o > 0; o >>= 1) m = fmaxf(m, __shfl_xor_sync(0xffffffffu, m, o));
    if ((tid & 31) == 0) red_max[tid >> 5] = m;
    __syncthreads();
    float mb = red_max[0];
#pragma unroll
    for (int i = 1; i < 8; i++) mb = fmaxf(mb, red_max[i]);

    float s = 0.0f;
#pragma unroll
    for (int i = 0; i < 4; i++) {
        v[i].x = __expf(v[i].x - mb); v[i].y = __expf(v[i].y - mb);
        v[i].z = __expf(v[i].z - mb); v[i].w = __expf(v[i].w - mb);
        s += (v[i].x + v[i].y) + (v[i].z + v[i].w);
    }
#pragma unroll
    for (int o = 16; o > 0; o >>= 1) s += __shfl_xor_sync(0xffffffffu, s, o);
    if ((tid & 31) == 0) red_sum[tid >> 5] = s;
    __syncthreads();
    float tot = 0.0f;
#pragma unroll
    for (int i = 0; i < 8; i++) tot += red_sum[i];
    const float inv = 1.0f / tot;

#pragma unroll
    for (int i = 0; i < 4; i++) {
        v[i].x *= inv; v[i].y *= inv; v[i].z *= inv; v[i].w *= inv;
        row[tid + i * 256] = v[i];
    }
}

// ---------------------------------------------------------------------------
extern "C" void kernel_launch(void* const* d_in, const int* in_sizes, int n_in,
                              void* d_out, int out_size)
{
    const float* q  = (const float*)d_in[0];
    const float* k  = (const float*)d_in[1];
    const float* v  = (const float*)d_in[2];
    const float* Wq = (const float*)d_in[3];
    const float* bq = (const float*)d_in[4];
    const float* Wk = (const float*)d_in[5];
    const float* bk = (const float*)d_in[6];
    const float* Wv = (const float*)d_in[7];
    const float* bv = (const float*)d_in[8];
    const float* Wo = (const float*)d_in[9];
    const float* bo = (const float*)d_in[10];

    float* out = (float*)d_out;
    const long OUT_ELEMS  = (long)NB * SEQ * DM;
    const long ATTN_ELEMS = (long)NH * NB * SEQ * SEQ;
    float* attn_out = nullptr;
    if ((long)out_size >= OUT_ELEMS + ATTN_ELEMS) attn_out = out + OUT_ELEMS;

    cudaFuncSetAttribute(proj_tc,    cudaFuncAttributeMaxDynamicSharedMemorySize, SMEM_BYTES);
    cudaFuncSetAttribute(scores_tc,  cudaFuncAttributeMaxDynamicSharedMemorySize, SMEM_BYTES);
    cudaFuncSetAttribute(av_tc,      cudaFuncAttributeMaxDynamicSharedMemorySize, SMEM_BYTES);
    cudaFuncSetAttribute(outproj_tc, cudaFuncAttributeMaxDynamicSharedMemorySize, SMEM_BYTES);

    trans_kernel<<<dim3(8, 32, 4),  256>>>(Wq, 0, DM, DK);
    trans_kernel<<<dim3(8, 32, 4),  256>>>(Wk, 1, DM, DK);
    trans_kernel<<<dim3(8, 32, 4),  256>>>(Wv, 2, DM, DK);
    trans_kernel<<<dim3(32, 32, 1), 256>>>(Wo, 3, DM, DM);

    proj_tc<<<dim3(1, 64, 12), 256, SMEM_BYTES>>>(q, k, v, bq, bk, bv);

    trans_kernel<<<dim3(8, 128, 8), 256>>>(nullptr, 4, SEQ, DK);

    scores_tc<<<dim3(32, 16, 8), 256, SMEM_BYTES>>>(attn_out);

    softmax_kernel<<<dim3(NH * NB * SEQ), 256>>>(attn_out);

    av_tc<<<dim3(1, 32, 8), 256, SMEM_BYTES>>>(attn_out);

    outproj_tc<<<dim3(4, 64, 1), 256, SMEM_BYTES>>>(bo, out);
}